// round 16
// baseline (speedup 1.0000x reference)
#include <cuda_runtime.h>
#include <cuda_fp16.h>
#include <cstdint>

#define DM 1024
#define NH 16
#define DKH 64
#define BB 2
#define SS 2048
#define MTOT (BB*SS)

// ---------------- scratch (static device arrays: allocation-free) ----------
__device__ __half g_Xh[MTOT*DM];                 // X: fp16
__device__ __half g_Wh[4*DM*DM];                 // weights: fp16
__device__ __half g_Qh[MTOT*DM];                 // Q
__device__ __half g_Kh[MTOT*DM];                 // K
__device__ __half g_Vh[MTOT*DM];                 // V
__device__ __half g_Ah[MTOT*DM];                 // attn out (fp16)

// ---------------- helpers ----------------------------------------------------
__device__ __forceinline__ uint32_t smem_u32(const void* p) {
    uint32_t a;
    asm("{ .reg .u64 t; cvta.to.shared.u64 t, %1; cvt.u32.u64 %0, t; }" : "=r"(a) : "l"(p));
    return a;
}
#define CP_ASYNC16(dst, src) \
    asm volatile("cp.async.cg.shared.global [%0], [%1], 16;" :: "r"(dst), "l"(src))
#define CP_COMMIT()  asm volatile("cp.async.commit_group;" ::: "memory")
#define CP_WAIT1()   asm volatile("cp.async.wait_group 1;" ::: "memory")
#define CP_WAIT0()   asm volatile("cp.async.wait_group 0;" ::: "memory")

#define LDMX4(r0, r1, r2, r3, addr) \
    asm volatile("ldmatrix.sync.aligned.m8n8.x4.shared.b16 {%0,%1,%2,%3}, [%4];" \
        : "=r"(r0), "=r"(r1), "=r"(r2), "=r"(r3) : "r"(addr))
#define LDMX4T(r0, r1, r2, r3, addr) \
    asm volatile("ldmatrix.sync.aligned.m8n8.x4.trans.shared.b16 {%0,%1,%2,%3}, [%4];" \
        : "=r"(r0), "=r"(r1), "=r"(r2), "=r"(r3) : "r"(addr))

#define MMA16816(d, a, b0, b1) \
    asm volatile("mma.sync.aligned.m16n8k16.row.col.f32.f16.f16.f32 " \
        "{%0,%1,%2,%3},{%4,%5,%6,%7},{%8,%9},{%0,%1,%2,%3};" \
        : "+f"((d)[0]), "+f"((d)[1]), "+f"((d)[2]), "+f"((d)[3]) \
        : "r"((a)[0]), "r"((a)[1]), "r"((a)[2]), "r"((a)[3]), "r"(b0), "r"(b1))

__device__ __forceinline__ uint32_t pack2h(float a, float b) {
    __half2 H = __halves2half2(__float2half_rn(a), __float2half_rn(b));
    return *(uint32_t*)&H;
}

// ---------------- fused convert: fp32 -> fp16 (X + 4 weights) ---------------
#define NX4 (MTOT*DM/4)       // 1048576
#define NW4 (DM*DM/4)         // 262144
#define NCVT (NX4 + 4*NW4)    // 2097152

__global__ __launch_bounds__(256)
void convert_kernel(const float* __restrict__ x,
                    const float* __restrict__ Wq, const float* __restrict__ Wk,
                    const float* __restrict__ Wv, const float* __restrict__ Wo) {
    int i = blockIdx.x * 256 + threadIdx.x;
    if (i >= NCVT) return;
    if (i < NX4) {
        float4 v = *(const float4*)(x + (size_t)i * 4);
        *(uint2*)(g_Xh + (size_t)i * 4) = make_uint2(pack2h(v.x, v.y), pack2h(v.z, v.w));
    } else {
        int j = i - NX4;
        int w = j >> 18;
        int off = j & (NW4 - 1);
        const float* src = (w == 0) ? Wq : (w == 1) ? Wk : (w == 2) ? Wv : Wo;
        float4 v = *(const float4*)(src + (size_t)off * 4);
        __half* h = g_Wh + (size_t)w * DM * DM + (size_t)off * 4;
        *(uint2*)h = make_uint2(pack2h(v.x, v.y), pack2h(v.z, v.w));
    }
}

// ---------------- mma.sync fp16 GEMM: 128x128 tile, KC=64, 2-stage, 2 CTA/SM
#define TMM 128
#define TNN 128
#define KC 64
#define NCH (DM/KC)            // 16
#define ROWB 144               // 128B data + 16B pad
#define TILE_BYTES (128*ROWB)  // 18432
#define STAGE_BYTES (2*TILE_BYTES) // 36864
#define GEMM_SMEM (2*STAGE_BYTES)  // 73728

template<bool TP>
__global__ __launch_bounds__(256, 2)
void tc_gemm_kernel(float* __restrict__ Cout) {
    extern __shared__ char smem[];
    const uint32_t sb = smem_u32(smem);
    const int tid = threadIdx.x, wid = tid >> 5, lane = tid & 31;
    const int n0 = blockIdx.x * TNN, m0 = blockIdx.y * TMM, z = blockIdx.z;

    const __half* Ah = (TP ? g_Ah : g_Xh) + (size_t)m0 * DM;
    const __half* Bh = g_Wh + (size_t)(TP ? 3 : z) * DM * DM + (size_t)n0 * DM;
    __half* Ch = (z == 0) ? g_Qh : (z == 1) ? g_Kh : g_Vh;

    const int warp_m = (wid & 3) * 32;
    const int warp_n = (wid >> 2) * 64;

    float acc[2][8][4];
#pragma unroll
    for (int i = 0; i < 2; i++)
#pragma unroll
        for (int j = 0; j < 8; j++)
#pragma unroll
            for (int k = 0; k < 4; k++) acc[i][j][k] = 0.0f;

    auto load_chunk = [&](uint32_t st, int c) {
        const int q = tid & 7;
        const int rh = tid >> 3;
        const size_t koff = (size_t)c * KC * 2 + (size_t)q * 16;
        const char* a_h = (const char*)Ah + koff;
        const char* b_h = (const char*)Bh + koff;
#pragma unroll
        for (int rr = 0; rr < 4; rr++) {
            int row = rh + rr * 32;
            uint32_t off = row * ROWB + q * 16;
            CP_ASYNC16(st + off,              a_h + (size_t)row * (DM * 2));
            CP_ASYNC16(st + TILE_BYTES + off, b_h + (size_t)row * (DM * 2));
        }
    };

    load_chunk(sb, 0);               CP_COMMIT();
    load_chunk(sb + STAGE_BYTES, 1); CP_COMMIT();

    const int lrow = lane & 15;
    const int lcol = (lane >> 4) * 16;

#pragma unroll 1
    for (int c = 0; c < NCH; c++) {
        CP_WAIT1();
        __syncthreads();
        const uint32_t st = sb + (uint32_t)(c & 1) * STAGE_BYTES;
        const uint32_t aH = st + (warp_m + lrow) * ROWB + lcol;
        const uint32_t bH = st + TILE_BYTES + (warp_n + lrow) * ROWB + lcol;

#pragma unroll
        for (int ks = 0; ks < 4; ks++) {
            const int kb = ks * 32;
            uint32_t ah[2][4];
#pragma unroll
            for (int mt = 0; mt < 2; mt++)
                LDMX4(ah[mt][0], ah[mt][1], ah[mt][2], ah[mt][3], aH + mt * 16 * ROWB + kb);
            uint32_t bh[4][4];
#pragma unroll
            for (int bt = 0; bt < 4; bt++)
                LDMX4(bh[bt][0], bh[bt][1], bh[bt][2], bh[bt][3], bH + bt * 16 * ROWB + kb);
#pragma unroll
            for (int mt = 0; mt < 2; mt++) {
#pragma unroll
                for (int bt = 0; bt < 4; bt++) {
                    MMA16816(acc[mt][2*bt],   ah[mt], bh[bt][0], bh[bt][2]);
                    MMA16816(acc[mt][2*bt+1], ah[mt], bh[bt][1], bh[bt][3]);
                }
            }
        }
        __syncthreads();
        if (c + 2 < NCH) load_chunk(st, c + 2);
        CP_COMMIT();
    }
    CP_WAIT0();

    const int g = lane >> 2, tig = lane & 3;
#pragma unroll
    for (int mt = 0; mt < 2; mt++) {
#pragma unroll
        for (int nt = 0; nt < 8; nt++) {
            int ng = n0 + warp_n + nt * 8 + tig * 2;
#pragma unroll
            for (int rr = 0; rr < 2; rr++) {
                int m = m0 + warp_m + mt * 16 + g + rr * 8;
                float v0 = acc[mt][nt][rr * 2 + 0];
                float v1 = acc[mt][nt][rr * 2 + 1];
                if (!TP) {
                    int b = m >> 11, s = m & (SS - 1);
                    int hh = ng >> 6, d0 = ng & 63;
                    size_t idx = ((size_t)((b * NH + hh) * SS + s)) * DKH + d0;
                    *(uint32_t*)(Ch + idx) = pack2h(v0, v1);
                } else {
                    float* dst = Cout + (size_t)m * DM + ng;
                    dst[0] = v0; dst[1] = v1;
                }
            }
        }
    }
}

// ---------------- flash attention: R12 structure + diagonal-tile warp skip --
#define BQ 128
#define BK 128
#define FROWB 144
#define FTILE (128*FROWB)        // 18432
#define FSTAGE (2*FTILE)         // Kh, Vh = 36864
#define FLASH_SMEM (2*FSTAGE)    // 73728

__global__ __launch_bounds__(256)
void flash_kernel() {
    extern __shared__ char fsm[];
    const uint32_t sb = smem_u32(fsm);
    const int tid = threadIdx.x, w = tid >> 5, lane = tid & 31;
    const int qt = (int)gridDim.x - 1 - (int)blockIdx.x;
    const int h = blockIdx.y, b = blockIdx.z;
    const int q0 = qt * BQ;
    const int g = lane >> 2, tig = lane & 3;

    const size_t headoff = ((size_t)(b * NH + h) * SS) * DKH;
    const char* Qh_g = (const char*)(g_Qh + headoff + (size_t)q0 * DKH);
    const char* Kh_g = (const char*)(g_Kh + headoff);
    const char* Vh_g = (const char*)(g_Vh + headoff);

    // ---- stage Q (hi) through stage-0 K slot, build Q fragments (registers)
#pragma unroll
    for (int t = 0; t < 4; t++) {
        int c = tid + t * 256;
        int row = c >> 3, q8 = c & 7;
        uint32_t dst = sb + row * FROWB + q8 * 16;
        CP_ASYNC16(dst, Qh_g + (size_t)row * 128 + q8 * 16);
    }
    CP_COMMIT(); CP_WAIT0();
    __syncthreads();
    uint32_t qfh[4][4];
    {
        uint32_t qbase = sb + (w * 16 + (lane & 15)) * FROWB + (lane >> 4) * 16;
#pragma unroll
        for (int ks = 0; ks < 4; ks++)
            LDMX4(qfh[ks][0], qfh[ks][1], qfh[ks][2], qfh[ks][3], qbase + ks * 32);
    }
    __syncthreads();

    auto load_tile = [&](int kt) {
        const char* srcs[2] = { Kh_g, Vh_g };
        const size_t tile_off = (size_t)kt * BK * 128;
        uint32_t stb = sb + (uint32_t)(kt & 1) * FSTAGE;
#pragma unroll
        for (int t = 0; t < 8; t++) {
            int c = tid + t * 256;
            int tile = c >> 10, row = (c >> 3) & 127, q8 = c & 7;
            uint32_t dst = stb + tile * FTILE + row * FROWB + q8 * 16;
            CP_ASYNC16(dst, srcs[tile] + tile_off + (size_t)row * 128 + q8 * 16);
        }
    };
    load_tile(0); CP_COMMIT();
    if (qt >= 1) load_tile(1);
    CP_COMMIT();

    float m0v = -1e30f, m1v = -1e30f, l0v = 0.0f, l1v = 0.0f;
    float o[8][4];
#pragma unroll
    for (int i = 0; i < 8; i++)
#pragma unroll
        for (int j = 0; j < 4; j++) o[i][j] = 0.0f;

#pragma unroll 1
    for (int kt = 0; kt <= qt; kt++) {
        CP_WAIT1();
        __syncthreads();
        const uint32_t st = sb + (uint32_t)(kt & 1) * FSTAGE;
        // diagonal-tile skip: warp w owns q-rows [16w,16w+16); columns beyond
        // 16(w+1) are fully masked for those rows, so their mma/exp are skipped.
        const int lim = (kt == qt) ? (w + 1) : 8;   // in 16-column blocks

        // ---- S = Qh @ Kh^T ----
        float s[16][4];
#pragma unroll
        for (int i = 0; i < 16; i++)
#pragma unroll
            for (int j = 0; j < 4; j++) s[i][j] = 0.0f;

        const uint32_t kb = st + (lane & 15) * FROWB + (lane >> 4) * 16;
#pragma unroll
        for (int ks = 0; ks < 4; ks++) {
#pragma unroll
            for (int np = 0; np < 8; np++) {
                if (np < lim) {
                    uint32_t kh[4];
                    uint32_t addr = kb + np * 16 * FROWB + ks * 32;
                    LDMX4(kh[0], kh[1], kh[2], kh[3], addr);
                    MMA16816(s[2*np],   qfh[ks], kh[0], kh[2]);
                    MMA16816(s[2*np+1], qfh[ks], kh[1], kh[3]);
                }
            }
        }

        // ---- scale + causal mask ----
        if (kt == qt) {
            const int rg = 16 * w + g, rg8 = rg + 8;
#pragma unroll
            for (int nt = 0; nt < 16; nt++) {
                if (nt < 2 * lim) {
                    int c0 = nt * 8 + 2 * tig, c1 = c0 + 1;
                    s[nt][0] = (c0 > rg)  ? -1e9f : s[nt][0] * 0.125f;
                    s[nt][1] = (c1 > rg)  ? -1e9f : s[nt][1] * 0.125f;
                    s[nt][2] = (c0 > rg8) ? -1e9f : s[nt][2] * 0.125f;
                    s[nt][3] = (c1 > rg8) ? -1e9f : s[nt][3] * 0.125f;
                }
            }
        } else {
#pragma unroll
            for (int nt = 0; nt < 16; nt++)
#pragma unroll
                for (int j = 0; j < 4; j++) s[nt][j] *= 0.125f;
        }

        // ---- online softmax over valid columns (warp-local rows) ----
        float mx0 = -1e30f, mx1 = -1e30f;
#pragma unroll
        for (int nt = 0; nt < 16; nt++) {
            if (nt < 2 * lim) {
                mx0 = fmaxf(mx0, fmaxf(s[nt][0], s[nt][1]));
                mx1 = fmaxf(mx1, fmaxf(s[nt][2], s[nt][3]));
            }
        }
        mx0 = fmaxf(mx0, __shfl_xor_sync(0xffffffffu, mx0, 1));
        mx0 = fmaxf(mx0, __shfl_xor_sync(0xffffffffu, mx0, 2));
        mx1 = fmaxf(mx1, __shfl_xor_sync(0xffffffffu, mx1, 1));
        mx1 = fmaxf(mx1, __shfl_xor_sync(0xffffffffu, mx1, 2));
        float mn0 = fmaxf(m0v, mx0), mn1 = fmaxf(m1v, mx1);
        float a0 = __expf(m0v - mn0), a1 = __expf(m1v - mn1);
        m0v = mn0; m1v = mn1;

        float sum0 = 0.0f, sum1 = 0.0f;
#pragma unroll
        for (int nt = 0; nt < 16; nt++) {
            if (nt < 2 * lim) {
                s[nt][0] = __expf(s[nt][0] - mn0);
                s[nt][1] = __expf(s[nt][1] - mn0);
                s[nt][2] = __expf(s[nt][2] - mn1);
                s[nt][3] = __expf(s[nt][3] - mn1);
                sum0 += s[nt][0] + s[nt][1];
                sum1 += s[nt][2] + s[nt][3];
            }
        }
        sum0 += __shfl_xor_sync(0xffffffffu, sum0, 1);
        sum0 += __shfl_xor_sync(0xffffffffu, sum0, 2);
        sum1 += __shfl_xor_sync(0xffffffffu, sum1, 1);
        sum1 += __shfl_xor_sync(0xffffffffu, sum1, 2);
        l0v = l0v * a0 + sum0;
        l1v = l1v * a1 + sum1;
#pragma unroll
        for (int nt = 0; nt < 8; nt++) {
            o[nt][0] *= a0; o[nt][1] *= a0;
            o[nt][2] *= a1; o[nt][3] *= a1;
        }

        // ---- O += Ph @ Vh over valid key blocks ----
        const uint32_t vb = st + FTILE + (lane & 15) * FROWB + (lane >> 4) * 16;
#pragma unroll
        for (int ks2 = 0; ks2 < 8; ks2++) {
            if (ks2 < lim) {
                uint32_t pah[4];
                pah[0] = pack2h(s[2*ks2][0],   s[2*ks2][1]);
                pah[1] = pack2h(s[2*ks2][2],   s[2*ks2][3]);
                pah[2] = pack2h(s[2*ks2+1][0], s[2*ks2+1][1]);
                pah[3] = pack2h(s[2*ks2+1][2], s[2*ks2+1][3]);
                uint32_t va = vb + ks2 * 16 * FROWB;
#pragma unroll
                for (int dkp = 0; dkp < 4; dkp++) {
                    uint32_t vh[4];
                    LDMX4T(vh[0], vh[1], vh[2], vh[3], va + dkp * 32);
                    MMA16816(o[2*dkp],   pah, vh[0], vh[1]);
                    MMA16816(o[2*dkp+1], pah, vh[2], vh[3]);
                }
            }
        }

        __syncthreads();
        if (kt + 2 <= qt) load_tile(kt + 2);
        CP_COMMIT();
    }

    const float i0 = 1.0f / l0v, i1 = 1.0f / l1v;
    const int m = q0 + 16 * w + g;
#pragma unroll
    for (int nt = 0; nt < 8; nt++) {
        int col = h * 64 + nt * 8 + 2 * tig;
        size_t i_a = ((size_t)(b * SS + m)) * DM + col;
        size_t i_b = ((size_t)(b * SS + m + 8)) * DM + col;
        *(uint32_t*)(g_Ah + i_a) = pack2h(o[nt][0] * i0, o[nt][1] * i0);
        *(uint32_t*)(g_Ah + i_b) = pack2h(o[nt][2] * i1, o[nt][3] * i1);
    }
}

// ---------------- launch ----------------------------------------------------
extern "C" void kernel_launch(void* const* d_in, const int* in_sizes, int n_in,
                              void* d_out, int out_size) {
    const float* x  = (const float*)d_in[0];
    const float* Wq = (const float*)d_in[2];
    const float* Wk = (const float*)d_in[3];
    const float* Wv = (const float*)d_in[4];
    const float* Wo = (const float*)d_in[5];
    float* out = (float*)d_out;

    static bool attr_done = false;
    if (!attr_done) {
        cudaFuncSetAttribute(tc_gemm_kernel<false>, cudaFuncAttributeMaxDynamicSharedMemorySize, GEMM_SMEM);
        cudaFuncSetAttribute(tc_gemm_kernel<true>,  cudaFuncAttributeMaxDynamicSharedMemorySize, GEMM_SMEM);
        cudaFuncSetAttribute(flash_kernel, cudaFuncAttributeMaxDynamicSharedMemorySize, FLASH_SMEM);
        attr_done = true;
    }

    convert_kernel<<<(NCVT + 255) / 256, 256>>>(x, Wq, Wk, Wv, Wo);

    dim3 gqkv(DM / TNN, MTOT / TMM, 3);
    tc_gemm_kernel<false><<<gqkv, 256, GEMM_SMEM>>>(nullptr);

    dim3 gflash(SS / BQ, NH, BB);
    flash_kernel<<<gflash, 256, FLASH_SMEM>>>();

    dim3 gout(DM / TNN, MTOT / TMM, 1);
    tc_gemm_kernel<true><<<gout, 256, GEMM_SMEM>>>(out);
}

// round 17
// speedup vs baseline: 1.1982x; 1.1982x over previous
#include <cuda_runtime.h>
#include <cuda_fp16.h>
#include <cstdint>

#define DM 1024
#define NH 16
#define DKH 64
#define BB 2
#define SS 2048
#define MTOT (BB*SS)

// ---------------- scratch (static device arrays: allocation-free) ----------
// Q/K/V now stored flat [B,S,DM] (head h's 64 lanes are contiguous 128B).
__device__ __half g_Xh[MTOT*DM];                 // X: fp16
__device__ __half g_Wh[4*DM*DM];                 // weights: fp16
__device__ __half g_Qh[MTOT*DM];                 // Q [B,S,DM]
__device__ __half g_Kh[MTOT*DM];                 // K [B,S,DM]
__device__ __half g_Vh[MTOT*DM];                 // V [B,S,DM]
__device__ __half g_Ah[MTOT*DM];                 // attn out (fp16) [B,S,DM]

// ---------------- helpers ----------------------------------------------------
__device__ __forceinline__ uint32_t smem_u32(const void* p) {
    uint32_t a;
    asm("{ .reg .u64 t; cvta.to.shared.u64 t, %1; cvt.u32.u64 %0, t; }" : "=r"(a) : "l"(p));
    return a;
}
#define CP_ASYNC16(dst, src) \
    asm volatile("cp.async.cg.shared.global [%0], [%1], 16;" :: "r"(dst), "l"(src))
#define CP_COMMIT()  asm volatile("cp.async.commit_group;" ::: "memory")
#define CP_WAIT1()   asm volatile("cp.async.wait_group 1;" ::: "memory")
#define CP_WAIT0()   asm volatile("cp.async.wait_group 0;" ::: "memory")

#define LDMX4(r0, r1, r2, r3, addr) \
    asm volatile("ldmatrix.sync.aligned.m8n8.x4.shared.b16 {%0,%1,%2,%3}, [%4];" \
        : "=r"(r0), "=r"(r1), "=r"(r2), "=r"(r3) : "r"(addr))
#define LDMX4T(r0, r1, r2, r3, addr) \
    asm volatile("ldmatrix.sync.aligned.m8n8.x4.trans.shared.b16 {%0,%1,%2,%3}, [%4];" \
        : "=r"(r0), "=r"(r1), "=r"(r2), "=r"(r3) : "r"(addr))

#define MMA16816(d, a, b0, b1) \
    asm volatile("mma.sync.aligned.m16n8k16.row.col.f32.f16.f16.f32 " \
        "{%0,%1,%2,%3},{%4,%5,%6,%7},{%8,%9},{%0,%1,%2,%3};" \
        : "+f"((d)[0]), "+f"((d)[1]), "+f"((d)[2]), "+f"((d)[3]) \
        : "r"((a)[0]), "r"((a)[1]), "r"((a)[2]), "r"((a)[3]), "r"(b0), "r"(b1))

__device__ __forceinline__ uint32_t pack2h(float a, float b) {
    __half2 H = __halves2half2(__float2half_rn(a), __float2half_rn(b));
    return *(uint32_t*)&H;
}

// ---------------- fused convert: fp32 -> fp16 (X + 4 weights) ---------------
#define NX4 (MTOT*DM/4)       // 1048576
#define NW4 (DM*DM/4)         // 262144
#define NCVT (NX4 + 4*NW4)    // 2097152

__global__ __launch_bounds__(256)
void convert_kernel(const float* __restrict__ x,
                    const float* __restrict__ Wq, const float* __restrict__ Wk,
                    const float* __restrict__ Wv, const float* __restrict__ Wo) {
    int i = blockIdx.x * 256 + threadIdx.x;
    if (i >= NCVT) return;
    if (i < NX4) {
        float4 v = *(const float4*)(x + (size_t)i * 4);
        *(uint2*)(g_Xh + (size_t)i * 4) = make_uint2(pack2h(v.x, v.y), pack2h(v.z, v.w));
    } else {
        int j = i - NX4;
        int w = j >> 18;
        int off = j & (NW4 - 1);
        const float* src = (w == 0) ? Wq : (w == 1) ? Wk : (w == 2) ? Wv : Wo;
        float4 v = *(const float4*)(src + (size_t)off * 4);
        __half* h = g_Wh + (size_t)w * DM * DM + (size_t)off * 4;
        *(uint2*)h = make_uint2(pack2h(v.x, v.y), pack2h(v.z, v.w));
    }
}

// ---------------- mma.sync fp16 GEMM: 128x128 tile, KC=64, 2-stage, 2 CTA/SM
#define TMM 128
#define TNN 128
#define KC 64
#define NCH (DM/KC)            // 16
#define ROWB 144               // 128B data + 16B pad
#define TILE_BYTES (128*ROWB)  // 18432
#define STAGE_BYTES (2*TILE_BYTES) // 36864
#define GEMM_SMEM (2*STAGE_BYTES)  // 73728

template<bool TP>
__global__ __launch_bounds__(256, 2)
void tc_gemm_kernel(float* __restrict__ Cout) {
    extern __shared__ char smem[];
    const uint32_t sb = smem_u32(smem);
    const int tid = threadIdx.x, wid = tid >> 5, lane = tid & 31;
    const int n0 = blockIdx.x * TNN, m0 = blockIdx.y * TMM, z = blockIdx.z;

    const __half* Ah = (TP ? g_Ah : g_Xh) + (size_t)m0 * DM;
    const __half* Bh = g_Wh + (size_t)(TP ? 3 : z) * DM * DM + (size_t)n0 * DM;
    __half* Ch = (z == 0) ? g_Qh : (z == 1) ? g_Kh : g_Vh;

    const int warp_m = (wid & 3) * 32;
    const int warp_n = (wid >> 2) * 64;

    float acc[2][8][4];
#pragma unroll
    for (int i = 0; i < 2; i++)
#pragma unroll
        for (int j = 0; j < 8; j++)
#pragma unroll
            for (int k = 0; k < 4; k++) acc[i][j][k] = 0.0f;

    auto load_chunk = [&](uint32_t st, int c) {
        const int q = tid & 7;
        const int rh = tid >> 3;
        const size_t koff = (size_t)c * KC * 2 + (size_t)q * 16;
        const char* a_h = (const char*)Ah + koff;
        const char* b_h = (const char*)Bh + koff;
#pragma unroll
        for (int rr = 0; rr < 4; rr++) {
            int row = rh + rr * 32;
            uint32_t off = row * ROWB + q * 16;
            CP_ASYNC16(st + off,              a_h + (size_t)row * (DM * 2));
            CP_ASYNC16(st + TILE_BYTES + off, b_h + (size_t)row * (DM * 2));
        }
    };

    load_chunk(sb, 0);               CP_COMMIT();
    load_chunk(sb + STAGE_BYTES, 1); CP_COMMIT();

    const int lrow = lane & 15;
    const int lcol = (lane >> 4) * 16;

#pragma unroll 1
    for (int c = 0; c < NCH; c++) {
        CP_WAIT1();
        __syncthreads();
        const uint32_t st = sb + (uint32_t)(c & 1) * STAGE_BYTES;
        const uint32_t aH = st + (warp_m + lrow) * ROWB + lcol;
        const uint32_t bH = st + TILE_BYTES + (warp_n + lrow) * ROWB + lcol;

#pragma unroll
        for (int ks = 0; ks < 4; ks++) {
            const int kb = ks * 32;
            uint32_t ah[2][4];
#pragma unroll
            for (int mt = 0; mt < 2; mt++)
                LDMX4(ah[mt][0], ah[mt][1], ah[mt][2], ah[mt][3], aH + mt * 16 * ROWB + kb);
            uint32_t bh[4][4];
#pragma unroll
            for (int bt = 0; bt < 4; bt++)
                LDMX4(bh[bt][0], bh[bt][1], bh[bt][2], bh[bt][3], bH + bt * 16 * ROWB + kb);
#pragma unroll
            for (int mt = 0; mt < 2; mt++) {
#pragma unroll
                for (int bt = 0; bt < 4; bt++) {
                    MMA16816(acc[mt][2*bt],   ah[mt], bh[bt][0], bh[bt][2]);
                    MMA16816(acc[mt][2*bt+1], ah[mt], bh[bt][1], bh[bt][3]);
                }
            }
        }
        __syncthreads();
        if (c + 2 < NCH) load_chunk(st, c + 2);
        CP_COMMIT();
    }
    CP_WAIT0();

    const int g = lane >> 2, tig = lane & 3;
#pragma unroll
    for (int mt = 0; mt < 2; mt++) {
#pragma unroll
        for (int nt = 0; nt < 8; nt++) {
            int ng = n0 + warp_n + nt * 8 + tig * 2;
#pragma unroll
            for (int rr = 0; rr < 2; rr++) {
                int m = m0 + warp_m + mt * 16 + g + rr * 8;
                float v0 = acc[mt][nt][rr * 2 + 0];
                float v1 = acc[mt][nt][rr * 2 + 1];
                if (!TP) {
                    // flat [B,S,DM] layout: same addressing as outproj path
                    *(uint32_t*)(Ch + (size_t)m * DM + ng) = pack2h(v0, v1);
                } else {
                    float* dst = Cout + (size_t)m * DM + ng;
                    dst[0] = v0; dst[1] = v1;
                }
            }
        }
    }
}

// ---------------- flash attention: R12 structure, flat-layout loads ---------
#define BQ 128
#define BK 128
#define FROWB 144
#define FTILE (128*FROWB)        // 18432
#define FSTAGE (2*FTILE)         // Kh, Vh = 36864
#define FLASH_SMEM (2*FSTAGE)    // 73728
#define GROW (DM*2)              // global row stride in bytes (flat layout)

__global__ __launch_bounds__(256)
void flash_kernel() {
    extern __shared__ char fsm[];
    const uint32_t sb = smem_u32(fsm);
    const int tid = threadIdx.x, w = tid >> 5, lane = tid & 31;
    const int qt = (int)gridDim.x - 1 - (int)blockIdx.x;
    const int h = blockIdx.y, b = blockIdx.z;
    const int q0 = qt * BQ;
    const int g = lane >> 2, tig = lane & 3;

    const size_t rowbase = (size_t)(b * SS);
    const char* Qh_g = (const char*)(g_Qh + (rowbase + q0) * DM + h * DKH);
    const char* Kh_g = (const char*)(g_Kh + rowbase * DM + h * DKH);
    const char* Vh_g = (const char*)(g_Vh + rowbase * DM + h * DKH);

    // ---- stage Q (hi) through stage-0 K slot, build Q fragments (registers)
#pragma unroll
    for (int t = 0; t < 4; t++) {
        int c = tid + t * 256;
        int row = c >> 3, q8 = c & 7;
        uint32_t dst = sb + row * FROWB + q8 * 16;
        CP_ASYNC16(dst, Qh_g + (size_t)row * GROW + q8 * 16);
    }
    CP_COMMIT(); CP_WAIT0();
    __syncthreads();
    uint32_t qfh[4][4];
    {
        uint32_t qbase = sb + (w * 16 + (lane & 15)) * FROWB + (lane >> 4) * 16;
#pragma unroll
        for (int ks = 0; ks < 4; ks++)
            LDMX4(qfh[ks][0], qfh[ks][1], qfh[ks][2], qfh[ks][3], qbase + ks * 32);
    }
    __syncthreads();

    auto load_tile = [&](int kt) {
        const char* srcs[2] = { Kh_g, Vh_g };
        const size_t tile_off = (size_t)kt * BK * GROW;
        uint32_t stb = sb + (uint32_t)(kt & 1) * FSTAGE;
#pragma unroll
        for (int t = 0; t < 8; t++) {
            int c = tid + t * 256;
            int tile = c >> 10, row = (c >> 3) & 127, q8 = c & 7;
            uint32_t dst = stb + tile * FTILE + row * FROWB + q8 * 16;
            CP_ASYNC16(dst, srcs[tile] + tile_off + (size_t)row * GROW + q8 * 16);
        }
    };
    load_tile(0); CP_COMMIT();
    if (qt >= 1) load_tile(1);
    CP_COMMIT();

    float m0v = -1e30f, m1v = -1e30f, l0v = 0.0f, l1v = 0.0f;
    float o[8][4];
#pragma unroll
    for (int i = 0; i < 8; i++)
#pragma unroll
        for (int j = 0; j < 4; j++) o[i][j] = 0.0f;

#pragma unroll 1
    for (int kt = 0; kt <= qt; kt++) {
        CP_WAIT1();
        __syncthreads();
        const uint32_t st = sb + (uint32_t)(kt & 1) * FSTAGE;

        // ---- S = Qh @ Kh^T ----
        float s[16][4];
#pragma unroll
        for (int i = 0; i < 16; i++)
#pragma unroll
            for (int j = 0; j < 4; j++) s[i][j] = 0.0f;

        const uint32_t kb = st + (lane & 15) * FROWB + (lane >> 4) * 16;
#pragma unroll
        for (int ks = 0; ks < 4; ks++) {
#pragma unroll
            for (int np = 0; np < 8; np++) {
                uint32_t kh[4];
                uint32_t addr = kb + np * 16 * FROWB + ks * 32;
                LDMX4(kh[0], kh[1], kh[2], kh[3], addr);
                MMA16816(s[2*np],   qfh[ks], kh[0], kh[2]);
                MMA16816(s[2*np+1], qfh[ks], kh[1], kh[3]);
            }
        }

        // ---- scale + causal mask ----
        if (kt == qt) {
            const int rg = 16 * w + g, rg8 = rg + 8;
#pragma unroll
            for (int nt = 0; nt < 16; nt++) {
                int c0 = nt * 8 + 2 * tig, c1 = c0 + 1;
                s[nt][0] = (c0 > rg)  ? -1e9f : s[nt][0] * 0.125f;
                s[nt][1] = (c1 > rg)  ? -1e9f : s[nt][1] * 0.125f;
                s[nt][2] = (c0 > rg8) ? -1e9f : s[nt][2] * 0.125f;
                s[nt][3] = (c1 > rg8) ? -1e9f : s[nt][3] * 0.125f;
            }
        } else {
#pragma unroll
            for (int nt = 0; nt < 16; nt++)
#pragma unroll
                for (int j = 0; j < 4; j++) s[nt][j] *= 0.125f;
        }

        // ---- online softmax (warp-local rows) ----
        float mx0 = -1e30f, mx1 = -1e30f;
#pragma unroll
        for (int nt = 0; nt < 16; nt++) {
            mx0 = fmaxf(mx0, fmaxf(s[nt][0], s[nt][1]));
            mx1 = fmaxf(mx1, fmaxf(s[nt][2], s[nt][3]));
        }
        mx0 = fmaxf(mx0, __shfl_xor_sync(0xffffffffu, mx0, 1));
        mx0 = fmaxf(mx0, __shfl_xor_sync(0xffffffffu, mx0, 2));
        mx1 = fmaxf(mx1, __shfl_xor_sync(0xffffffffu, mx1, 1));
        mx1 = fmaxf(mx1, __shfl_xor_sync(0xffffffffu, mx1, 2));
        float mn0 = fmaxf(m0v, mx0), mn1 = fmaxf(m1v, mx1);
        float a0 = __expf(m0v - mn0), a1 = __expf(m1v - mn1);
        m0v = mn0; m1v = mn1;

        float sum0 = 0.0f, sum1 = 0.0f;
#pragma unroll
        for (int nt = 0; nt < 16; nt++) {
            s[nt][0] = __expf(s[nt][0] - mn0);
            s[nt][1] = __expf(s[nt][1] - mn0);
            s[nt][2] = __expf(s[nt][2] - mn1);
            s[nt][3] = __expf(s[nt][3] - mn1);
            sum0 += s[nt][0] + s[nt][1];
            sum1 += s[nt][2] + s[nt][3];
        }
        sum0 += __shfl_xor_sync(0xffffffffu, sum0, 1);
        sum0 += __shfl_xor_sync(0xffffffffu, sum0, 2);
        sum1 += __shfl_xor_sync(0xffffffffu, sum1, 1);
        sum1 += __shfl_xor_sync(0xffffffffu, sum1, 2);
        l0v = l0v * a0 + sum0;
        l1v = l1v * a1 + sum1;
#pragma unroll
        for (int nt = 0; nt < 8; nt++) {
            o[nt][0] *= a0; o[nt][1] *= a0;
            o[nt][2] *= a1; o[nt][3] *= a1;
        }

        // ---- O += Ph @ Vh ----
        const uint32_t vb = st + FTILE + (lane & 15) * FROWB + (lane >> 4) * 16;
#pragma unroll
        for (int ks2 = 0; ks2 < 8; ks2++) {
            uint32_t pah[4];
            pah[0] = pack2h(s[2*ks2][0],   s[2*ks2][1]);
            pah[1] = pack2h(s[2*ks2][2],   s[2*ks2][3]);
            pah[2] = pack2h(s[2*ks2+1][0], s[2*ks2+1][1]);
            pah[3] = pack2h(s[2*ks2+1][2], s[2*ks2+1][3]);
            uint32_t va = vb + ks2 * 16 * FROWB;
#pragma unroll
            for (int dkp = 0; dkp < 4; dkp++) {
                uint32_t vh[4];
                LDMX4T(vh[0], vh[1], vh[2], vh[3], va + dkp * 32);
                MMA16816(o[2*dkp],   pah, vh[0], vh[1]);
                MMA16816(o[2*dkp+1], pah, vh[2], vh[3]);
            }
        }

        __syncthreads();
        if (kt + 2 <= qt) load_tile(kt + 2);
        CP_COMMIT();
    }

    const float i0 = 1.0f / l0v, i1 = 1.0f / l1v;
    const int m = q0 + 16 * w + g;
#pragma unroll
    for (int nt = 0; nt < 8; nt++) {
        int col = h * 64 + nt * 8 + 2 * tig;
        size_t i_a = ((size_t)(b * SS + m)) * DM + col;
        size_t i_b = ((size_t)(b * SS + m + 8)) * DM + col;
        *(uint32_t*)(g_Ah + i_a) = pack2h(o[nt][0] * i0, o[nt][1] * i0);
        *(uint32_t*)(g_Ah + i_b) = pack2h(o[nt][2] * i1, o[nt][3] * i1);
    }
}

// ---------------- launch ----------------------------------------------------
extern "C" void kernel_launch(void* const* d_in, const int* in_sizes, int n_in,
                              void* d_out, int out_size) {
    const float* x  = (const float*)d_in[0];
    const float* Wq = (const float*)d_in[2];
    const float* Wk = (const float*)d_in[3];
    const float* Wv = (const float*)d_in[4];
    const float* Wo = (const float*)d_in[5];
    float* out = (float*)d_out;

    static bool attr_done = false;
    if (!attr_done) {
        cudaFuncSetAttribute(tc_gemm_kernel<false>, cudaFuncAttributeMaxDynamicSharedMemorySize, GEMM_SMEM);
        cudaFuncSetAttribute(tc_gemm_kernel<true>,  cudaFuncAttributeMaxDynamicSharedMemorySize, GEMM_SMEM);
        cudaFuncSetAttribute(flash_kernel, cudaFuncAttributeMaxDynamicSharedMemorySize, FLASH_SMEM);
        attr_done = true;
    }

    convert_kernel<<<(NCVT + 255) / 256, 256>>>(x, Wq, Wk, Wv, Wo);

    dim3 gqkv(DM / TNN, MTOT / TMM, 3);
    tc_gemm_kernel<false><<<gqkv, 256, GEMM_SMEM>>>(nullptr);

    dim3 gflash(SS / BQ, NH, BB);
    flash_kernel<<<gflash, 256, FLASH_SMEM>>>();

    dim3 gout(DM / TNN, MTOT / TMM, 1);
    tc_gemm_kernel<true><<<gout, 256, GEMM_SMEM>>>(out);
}